// round 2
// baseline (speedup 1.0000x reference)
#include <cuda_runtime.h>
#include <math.h>

#define NN 50000
#define EE 800000
#define CC 64
#define SS 10
#define HH 64

// -------- scratch (static device globals; no allocation) --------
__device__ float g_h0[NN * CC];        // up-projected scalars   [n][c]
__device__ float g_h1[NN * 3 * CC];    // up-projected vectors   [n][i][c]
__device__ float g_T0[NN * CC];        // scattered messages     [n][c]
__device__ float g_T1[NN * 3 * CC];    // scattered messages     [n][i][c]

// -------- f32x2 packed math helpers (sm_100+) --------
__device__ __forceinline__ unsigned long long dup2(float x) {
    unsigned long long r;
    asm("mov.b64 %0, {%1, %1};" : "=l"(r) : "r"(__float_as_uint(x)));
    return r;
}
__device__ __forceinline__ void fma2(unsigned long long& d, unsigned long long a,
                                     unsigned long long b) {
    asm("fma.rn.f32x2 %0, %1, %2, %0;" : "+l"(d) : "l"(a), "l"(b));
}
__device__ __forceinline__ void unpack2(unsigned long long v, float& lo, float& hi) {
    unsigned int a, b;
    asm("mov.b64 {%0, %1}, %2;" : "=r"(a), "=r"(b) : "l"(v));
    lo = __uint_as_float(a);
    hi = __uint_as_float(b);
}

// ============================================================
// Zero the scatter targets. T0: 800000 float4, T1: 2400000 float4.
// Launched with 12500*256 = 3.2M threads.
// ============================================================
__global__ void zero_kernel() {
    const int i = blockIdx.x * 256 + threadIdx.x;
    const float4 z = make_float4(0.f, 0.f, 0.f, 0.f);
    if (i < (NN * CC) / 4)
        reinterpret_cast<float4*>(g_T0)[i] = z;
    if (i < (NN * 3 * CC) / 4)
        reinterpret_cast<float4*>(g_T1)[i] = z;
}

// ============================================================
// Up-projection: h0 = nf0 @ Wup0 ; h1[n,o,i] = sum_c nf1[n,c,i] Wup1[c,o]
// stored as g_h1[n][i][o]
// ============================================================
__global__ void __launch_bounds__(256) up_kernel(
    const float* __restrict__ nf0, const float* __restrict__ nf1,
    const float* __restrict__ Wup0, const float* __restrict__ Wup1) {
    extern __shared__ float sm[];
    float* sW0  = sm;            // 4096
    float* sW1m = sm + 4096;     // 4096
    float* s0   = sm + 8192;     // 32*64   = 2048
    float* s1   = sm + 10240;    // 32*192  = 6144
    const int tid  = threadIdx.x;
    const int base = blockIdx.x * 32;

    for (int i = tid; i < 4096; i += 256) { sW0[i] = Wup0[i]; sW1m[i] = Wup1[i]; }
    for (int i = tid; i < 2048; i += 256) {
        size_t g = (size_t)base * 64 + i;
        s0[i] = (g < (size_t)NN * 64) ? nf0[g] : 0.f;
    }
    for (int i = tid; i < 6144; i += 256) {
        size_t g = (size_t)base * 192 + i;
        s1[i] = (g < (size_t)NN * 192) ? nf1[g] : 0.f;
    }
    __syncthreads();

    const int o = tid & 63, ng = tid >> 6;
    for (int nl = ng; nl < 32; nl += 4) {
        const int n = base + nl;
        if (n >= NN) break;
        float a = 0.f;
#pragma unroll
        for (int c = 0; c < 64; c++) a += s0[nl * 64 + c] * sW0[c * 64 + o];
        g_h0[(size_t)n * 64 + o] = a;
#pragma unroll
        for (int i3 = 0; i3 < 3; i3++) {
            float b = 0.f;
#pragma unroll 16
            for (int c = 0; c < 64; c++)
                b += s1[nl * 192 + c * 3 + i3] * sW1m[c * 64 + o];
            g_h1[((size_t)n * 3 + i3) * 64 + o] = b;
        }
    }
}

// ============================================================
// Edge kernel: radial MLP (f32x2 packed) + tensor-product messages + scatter
// one edge per thread, 256 threads / block, E = 3125 * 256 exactly
// ============================================================
__global__ void __launch_bounds__(256, 1) edge_kernel(
    const float* __restrict__ ef, const float* __restrict__ ea1,
    const float* __restrict__ cut, const float* __restrict__ W1,
    const float* __restrict__ W2, const int* __restrict__ ei) {
    extern __shared__ float sm[];
    float* sW1  = sm;                  // 8*64      = 512
    float* sW2  = sm + 512;            // 64*256    = 16384
    float* sHid = sm + 512 + 16384;    // 64*256thr = 16384
    const int tid = threadIdx.x;

    for (int i = tid; i < 512; i += 256)   sW1[i] = W1[i];
    for (int i = tid; i < 16384; i += 256) sW2[i] = W2[i];
    __syncthreads();

    const int e = blockIdx.x * 256 + tid;

    // hidden = silu(ef @ W1), staged per-thread in smem (lane-striped)
    const float4 f0 = *(const float4*)(ef + (size_t)e * 8);
    const float4 f1 = *(const float4*)(ef + (size_t)e * 8 + 4);
#pragma unroll 8
    for (int h = 0; h < HH; h++) {
        float a = f0.x * sW1[h]       + f0.y * sW1[64 + h]
                + f0.z * sW1[128 + h] + f0.w * sW1[192 + h]
                + f1.x * sW1[256 + h] + f1.y * sW1[320 + h]
                + f1.z * sW1[384 + h] + f1.w * sW1[448 + h];
        sHid[h * 256 + tid] = a / (1.f + __expf(-a));
    }
    // same-thread RAW on smem: no barrier needed

    const int src = ei[e];
    const int dst = ei[EE + e];
    const float cu = cut[e];
    const float sx = ea1[e * 3 + 0], sy = ea1[e * 3 + 1], sz = ea1[e * 3 + 2];
    const float* __restrict__ h0row = g_h0 + (size_t)src * 64;
    const float* __restrict__ h1row = g_h1 + (size_t)src * 192;
    float* T0row = g_T0 + (size_t)dst * 64;
    float* T1row = g_T1 + (size_t)dst * 192;

    for (int cb = 0; cb < 64; cb += 16) {
        // w[g][c] for 4 path-groups x 16 channels, packed as 8 f32x2 per group
        unsigned long long acc[32];
#pragma unroll
        for (int i = 0; i < 32; i++) acc[i] = 0ULL;

#pragma unroll 4
        for (int h = 0; h < HH; h++) {
            unsigned long long a = dup2(sHid[h * 256 + tid]);
            const float* row = sW2 + h * 256 + cb;
#pragma unroll
            for (int g = 0; g < 4; g++) {
#pragma unroll
                for (int q = 0; q < 4; q++) {
                    ulonglong2 w = *(const ulonglong2*)(row + g * 64 + q * 4);
                    fma2(acc[g * 8 + q * 2 + 0], a, w.x);
                    fma2(acc[g * 8 + q * 2 + 1], a, w.y);
                }
            }
        }

        // messages + atomic scatter for this 16-channel chunk
#pragma unroll
        for (int p = 0; p < 8; p++) {
            const int c = cb + 2 * p;
            float w00a, w00b, w11a, w11b, w01a, w01b, w10a, w10b;
            unpack2(acc[0 * 8 + p], w00a, w00b);
            unpack2(acc[1 * 8 + p], w11a, w11b);
            unpack2(acc[2 * 8 + p], w01a, w01b);
            unpack2(acc[3 * 8 + p], w10a, w10b);
            const float2 h0v = *(const float2*)(h0row + c);
            const float2 hx  = *(const float2*)(h1row + 0 * 64 + c);
            const float2 hy  = *(const float2*)(h1row + 1 * 64 + c);
            const float2 hz  = *(const float2*)(h1row + 2 * 64 + c);
            {
                const float dotv = hx.x * sx + hy.x * sy + hz.x * sz;
                atomicAdd(&T0row[c], (w00a * h0v.x + w11a * dotv) * cu);
                const float a01 = w01a * h0v.x * cu;
                const float a10 = w10a * cu;
                atomicAdd(&T1row[c],           a01 * sx + a10 * hx.x);
                atomicAdd(&T1row[64 + c],      a01 * sy + a10 * hy.x);
                atomicAdd(&T1row[128 + c],     a01 * sz + a10 * hz.x);
            }
            {
                const float dotv = hx.y * sx + hy.y * sy + hz.y * sz;
                atomicAdd(&T0row[c + 1], (w00b * h0v.y + w11b * dotv) * cu);
                const float a01 = w01b * h0v.y * cu;
                const float a10 = w10b * cu;
                atomicAdd(&T1row[c + 1],       a01 * sx + a10 * hx.y);
                atomicAdd(&T1row[64 + c + 1],  a01 * sy + a10 * hy.y);
                atomicAdd(&T1row[128 + c + 1], a01 * sz + a10 * hz.y);
            }
        }
    }
}

// ============================================================
// Node epilogue 0: mi0 + res0 (Wsc0 fully resident in smem)
// out[n][0:64] = mi0 ; out[n][256:320] = res0
// ============================================================
__global__ void __launch_bounds__(256) node0_kernel(
    const float* __restrict__ attrs, const float* __restrict__ Wsc0,
    float* __restrict__ out) {
    extern __shared__ float sm[];
    float* sW  = sm;              // 10*64*64 = 40960
    float* sMi = sm + 40960;      // 4*64
    int*   sSp = (int*)(sMi + 256);
    const int tid = threadIdx.x;
    for (int i = tid; i < SS * CC * CC; i += 256) sW[i] = Wsc0[i];
    __syncthreads();

    const int o = tid & 63, ng = tid >> 6;
    for (int base = blockIdx.x * 4; base < NN; base += gridDim.x * 4) {
        const int n = base + ng;   // NN % 4 == 0, always valid
        sMi[ng * 64 + o] = g_T0[(size_t)n * 64 + o] * (1.f / 16.f);
        if (o == 0) {
            const float* a = attrs + (size_t)n * SS;
            int s = 0;
            for (int t = 1; t < SS; t++) if (a[t] > 0.5f) s = t;
            sSp[ng] = s;
        }
        __syncthreads();
        const float* W = sW + sSp[ng] * 4096;
        float acc = 0.f;
#pragma unroll
        for (int c = 0; c < 64; c++) acc += sMi[ng * 64 + c] * W[c * 64 + o];
        float* orow = out + (size_t)n * 512;
        orow[o]       = sMi[ng * 64 + o];
        orow[256 + o] = acc;
        __syncthreads();
    }
}

// ============================================================
// Node epilogue 1: mi1 + res1 (Wsc1 fully resident in smem)
// out[n][64 + c*3 + i] = mi1[c][i] ; out[n][320 + o*3 + i] = res1[o][i]
// ============================================================
__global__ void __launch_bounds__(256) node1_kernel(
    const float* __restrict__ attrs, const float* __restrict__ Wsc1,
    float* __restrict__ out) {
    extern __shared__ float sm[];
    float* sW  = sm;              // 40960
    float* sMi = sm + 40960;      // 4*3*64 = 768
    int*   sSp = (int*)(sMi + 768);
    const int tid = threadIdx.x;
    for (int i = tid; i < SS * CC * CC; i += 256) sW[i] = Wsc1[i];
    __syncthreads();

    const int o = tid & 63, ng = tid >> 6;
    for (int base = blockIdx.x * 4; base < NN; base += gridDim.x * 4) {
        const int n = base + ng;
#pragma unroll
        for (int i3 = 0; i3 < 3; i3++)
            sMi[ng * 192 + i3 * 64 + o] =
                g_T1[((size_t)n * 3 + i3) * 64 + o] * (1.f / 16.f);
        if (o == 0) {
            const float* a = attrs + (size_t)n * SS;
            int s = 0;
            for (int t = 1; t < SS; t++) if (a[t] > 0.5f) s = t;
            sSp[ng] = s;
        }
        __syncthreads();
        const float* W = sW + sSp[ng] * 4096;
        float a0 = 0.f, a1 = 0.f, a2 = 0.f;
#pragma unroll
        for (int c = 0; c < 64; c++) {
            const float wv = W[c * 64 + o];
            a0 += sMi[ng * 192 + c] * wv;
            a1 += sMi[ng * 192 + 64 + c] * wv;
            a2 += sMi[ng * 192 + 128 + c] * wv;
        }
        float* orow = out + (size_t)n * 512;
        orow[64 + o * 3 + 0]  = sMi[ng * 192 + o];
        orow[64 + o * 3 + 1]  = sMi[ng * 192 + 64 + o];
        orow[64 + o * 3 + 2]  = sMi[ng * 192 + 128 + o];
        orow[320 + o * 3 + 0] = a0;
        orow[320 + o * 3 + 1] = a1;
        orow[320 + o * 3 + 2] = a2;
        __syncthreads();
    }
}

// ============================================================
extern "C" void kernel_launch(void* const* d_in, const int* in_sizes, int n_in,
                              void* d_out, int out_size) {
    const float* nf0   = (const float*)d_in[0];
    const float* nf1   = (const float*)d_in[1];
    const float* attrs = (const float*)d_in[2];
    const float* ef    = (const float*)d_in[3];
    const float* ea1   = (const float*)d_in[4];
    const float* cut   = (const float*)d_in[5];
    const float* Wup0  = (const float*)d_in[6];
    const float* Wup1  = (const float*)d_in[7];
    const float* W1    = (const float*)d_in[8];
    const float* W2    = (const float*)d_in[9];
    const float* Wsc0  = (const float*)d_in[10];
    const float* Wsc1  = (const float*)d_in[11];
    // d_in[12], d_in[13] are Q0/Q1 identity projectors (no-op)
    const int*   ei    = (const int*)d_in[14];
    float* out = (float*)d_out;

    const int up_smem   = 16384 * 4;                 // 64 KB
    const int edge_smem = (512 + 16384 + 16384) * 4; // 130 KB
    const int c0_smem   = (40960 + 256) * 4 + 32;    // ~161 KB
    const int c1_smem   = (40960 + 768) * 4 + 32;    // ~163 KB
    cudaFuncSetAttribute(up_kernel,    cudaFuncAttributeMaxDynamicSharedMemorySize, up_smem);
    cudaFuncSetAttribute(edge_kernel,  cudaFuncAttributeMaxDynamicSharedMemorySize, edge_smem);
    cudaFuncSetAttribute(node0_kernel, cudaFuncAttributeMaxDynamicSharedMemorySize, c0_smem);
    cudaFuncSetAttribute(node1_kernel, cudaFuncAttributeMaxDynamicSharedMemorySize, c1_smem);

    zero_kernel<<<12500, 256>>>();
    up_kernel<<<(NN + 31) / 32, 256, up_smem>>>(nf0, nf1, Wup0, Wup1);
    edge_kernel<<<EE / 256, 256, edge_smem>>>(ef, ea1, cut, W1, W2, ei);
    node0_kernel<<<152, 256, c0_smem>>>(attrs, Wsc0, out);
    node1_kernel<<<152, 256, c1_smem>>>(attrs, Wsc1, out);
}

// round 3
// speedup vs baseline: 2.1003x; 2.1003x over previous
#include <cuda_runtime.h>
#include <math.h>

#define NN 50000
#define EE 800000
#define CC 64
#define SS 10
#define HH 64

typedef unsigned long long ull;

// -------- scratch (static device globals; no allocation) --------
__device__ float g_h0[NN * CC];        // up-projected scalars   [n][c]
__device__ float g_h1[NN * 3 * CC];    // up-projected vectors   [n][i][c]
__device__ float g_T0[NN * CC];        // node messages (already /16)
__device__ float g_T1[NN * 3 * CC];
__device__ int   g_deg[NN];
__device__ int   g_off[NN + 1];
__device__ int   g_cur[NN];
__device__ int   g_perm[EE];

// -------- f32x2 packed math helpers (sm_100+) --------
__device__ __forceinline__ ull dup2(float x) {
    ull r;
    asm("mov.b64 %0, {%1, %1};" : "=l"(r) : "r"(__float_as_uint(x)));
    return r;
}
__device__ __forceinline__ void fma2(ull& d, ull a, ull b) {
    asm("fma.rn.f32x2 %0, %1, %2, %0;" : "+l"(d) : "l"(a), "l"(b));
}
__device__ __forceinline__ ull mul2(ull a, ull b) {
    ull d;
    asm("mul.rn.f32x2 %0, %1, %2;" : "=l"(d) : "l"(a), "l"(b));
    return d;
}
__device__ __forceinline__ void unpack2(ull v, float& lo, float& hi) {
    unsigned int a, b;
    asm("mov.b64 {%0, %1}, %2;" : "=r"(a), "=r"(b) : "l"(v));
    lo = __uint_as_float(a);
    hi = __uint_as_float(b);
}

// ============================================================
// CSR build
// ============================================================
__global__ void zero_deg_kernel() {
    int i = blockIdx.x * 256 + threadIdx.x;
    if (i < NN) g_deg[i] = 0;
}

__global__ void hist_kernel(const int* __restrict__ ei) {
    int e = blockIdx.x * 256 + threadIdx.x;   // E = 3125*256 exact
    atomicAdd(&g_deg[ei[EE + e]], 1);
}

__global__ void __launch_bounds__(1024) scan_kernel() {
    __shared__ int sp[1024];
    const int t = threadIdx.x;
    const int CH = (NN + 1023) / 1024;       // 49
    const int i0 = t * CH;
    const int i1 = min(i0 + CH, NN);
    int part = 0;
    for (int i = i0; i < i1; i++) part += g_deg[i];
    sp[t] = part;
    __syncthreads();
    // inclusive Hillis-Steele scan
    for (int off = 1; off < 1024; off <<= 1) {
        int v = (t >= off) ? sp[t - off] : 0;
        __syncthreads();
        sp[t] += v;
        __syncthreads();
    }
    int run = sp[t] - part;                  // exclusive base
    for (int i = i0; i < i1; i++) {
        g_off[i] = run;
        g_cur[i] = run;
        run += g_deg[i];
    }
    if (t == 0) g_off[NN] = EE;
}

__global__ void scatter_kernel(const int* __restrict__ ei) {
    int e = blockIdx.x * 256 + threadIdx.x;
    int pos = atomicAdd(&g_cur[ei[EE + e]], 1);
    g_perm[pos] = e;
}

// ============================================================
// Up-projection: h0 = nf0 @ Wup0 ; g_h1[n][i][o] = sum_c nf1[n,c,i] Wup1[c,o]
// ============================================================
__global__ void __launch_bounds__(256) up_kernel(
    const float* __restrict__ nf0, const float* __restrict__ nf1,
    const float* __restrict__ Wup0, const float* __restrict__ Wup1) {
    extern __shared__ float sm[];
    float* sW0  = sm;            // 4096
    float* sW1m = sm + 4096;     // 4096
    float* s0   = sm + 8192;     // 32*64
    float* s1   = sm + 10240;    // 32*192
    const int tid  = threadIdx.x;
    const int base = blockIdx.x * 32;

    for (int i = tid; i < 4096; i += 256) { sW0[i] = Wup0[i]; sW1m[i] = Wup1[i]; }
    for (int i = tid; i < 2048; i += 256) {
        size_t g = (size_t)base * 64 + i;
        s0[i] = (g < (size_t)NN * 64) ? nf0[g] : 0.f;
    }
    for (int i = tid; i < 6144; i += 256) {
        size_t g = (size_t)base * 192 + i;
        s1[i] = (g < (size_t)NN * 192) ? nf1[g] : 0.f;
    }
    __syncthreads();

    const int o = tid & 63, ng = tid >> 6;
    for (int nl = ng; nl < 32; nl += 4) {
        const int n = base + nl;
        if (n >= NN) break;
        float a = 0.f;
#pragma unroll
        for (int c = 0; c < 64; c++) a += s0[nl * 64 + c] * sW0[c * 64 + o];
        g_h0[(size_t)n * 64 + o] = a;
#pragma unroll
        for (int i3 = 0; i3 < 3; i3++) {
            float b = 0.f;
#pragma unroll 16
            for (int c = 0; c < 64; c++)
                b += s1[nl * 192 + c * 3 + i3] * sW1m[c * 64 + o];
            g_h1[((size_t)n * 3 + i3) * 64 + o] = b;
        }
    }
}

// ============================================================
// Fused node-centric kernel: warp per node, 4-edge batches.
// Per edge: radial MLP recompute + 64->256 GEMV (W2 smem, f32x2)
// + tensor-product message, accumulated in registers. No atomics.
// ============================================================
__global__ void __launch_bounds__(128) node_kernel(
    const float* __restrict__ ef, const float* __restrict__ ea1,
    const float* __restrict__ cut, const float* __restrict__ W1,
    const float* __restrict__ W2, const int* __restrict__ ei) {
    extern __shared__ float sm[];
    float* sW1  = sm;                 // 512
    float* sW2  = sm + 512;           // 16384 floats = 64KB
    float* sHid = sm + 512 + 16384;   // 4 warps * 4 edges * 64 = 1024
    const int tid = threadIdx.x;
    for (int i = tid; i < 512; i += 128)   sW1[i] = W1[i];
    for (int i = tid; i < 16384; i += 128) sW2[i] = W2[i];
    __syncthreads();

    const int wid = tid >> 5, lane = tid & 31;
    float* sH = sHid + wid * 256;
    const unsigned FULL = 0xffffffffu;
    const int l2 = 2 * lane;

    for (int node = blockIdx.x * 4 + wid; node < NN; node += gridDim.x * 4) {
        const int beg = g_off[node];
        const int end = g_off[node + 1];
        ull m0 = 0, m1x = 0, m1y = 0, m1z = 0;

        for (int b = beg; b < end; b += 4) {
            // lanes 0..3 stage edge b+lane (padded: cu=0 kills pad contributions)
            int src_ = 0;
            float cu_ = 0.f, sx_ = 0.f, sy_ = 0.f, sz_ = 0.f;
            float4 f0_ = make_float4(0.f, 0.f, 0.f, 0.f), f1_ = f0_;
            if (lane < 4) {
                const int idx = b + lane;
                const int ee  = g_perm[idx < end ? idx : b];
                src_ = ei[ee];
                cu_  = (idx < end) ? cut[ee] : 0.f;
                sx_  = ea1[ee * 3];
                sy_  = ea1[ee * 3 + 1];
                sz_  = ea1[ee * 3 + 2];
                f0_  = *(const float4*)(ef + (size_t)ee * 8);
                f1_  = *(const float4*)(ef + (size_t)ee * 8 + 4);
            }
            // hidden = silu(ef @ W1) for 4 edges (each lane: 2 hidden units/edge)
#pragma unroll
            for (int j = 0; j < 4; j++) {
                float fr[8];
                fr[0] = __shfl_sync(FULL, f0_.x, j);
                fr[1] = __shfl_sync(FULL, f0_.y, j);
                fr[2] = __shfl_sync(FULL, f0_.z, j);
                fr[3] = __shfl_sync(FULL, f0_.w, j);
                fr[4] = __shfl_sync(FULL, f1_.x, j);
                fr[5] = __shfl_sync(FULL, f1_.y, j);
                fr[6] = __shfl_sync(FULL, f1_.z, j);
                fr[7] = __shfl_sync(FULL, f1_.w, j);
                float a0 = 0.f, a1 = 0.f;
#pragma unroll
                for (int r = 0; r < 8; r++) {
                    float2 wv = *(const float2*)(sW1 + r * 64 + l2);
                    a0 = fmaf(fr[r], wv.x, a0);
                    a1 = fmaf(fr[r], wv.y, a1);
                }
                a0 = a0 / (1.f + __expf(-a0));
                a1 = a1 / (1.f + __expf(-a1));
                *(float2*)(sH + j * 64 + l2) = make_float2(a0, a1);
            }
            __syncwarp();

            // gather sender features (overlaps with h-loop below)
            ull gh0[4], ghx[4], ghy[4], ghz[4];
#pragma unroll
            for (int j = 0; j < 4; j++) {
                const int sj = __shfl_sync(FULL, src_, j);
                const float* p0 = g_h0 + (size_t)sj * 64 + l2;
                const float* p1 = g_h1 + (size_t)sj * 192 + l2;
                gh0[j] = *(const ull*)p0;
                ghx[j] = *(const ull*)p1;
                ghy[j] = *(const ull*)(p1 + 64);
                ghz[j] = *(const ull*)(p1 + 128);
            }

            // w = hid @ W2 for 4 edges; lane owns channel pair (2l, 2l+1)
            ull w00[4] = {0, 0, 0, 0}, w11[4] = {0, 0, 0, 0};
            ull w01[4] = {0, 0, 0, 0}, w10[4] = {0, 0, 0, 0};
            const float* basep = sW2 + l2;
#pragma unroll 4
            for (int h = 0; h < 64; h++) {
                const float* row = basep + h * 256;
                const ull b00 = *(const ull*)row;
                const ull b11 = *(const ull*)(row + 64);
                const ull b01 = *(const ull*)(row + 128);
                const ull b10 = *(const ull*)(row + 192);
#pragma unroll
                for (int j = 0; j < 4; j++) {
                    const ull a = dup2(sH[j * 64 + h]);
                    fma2(w00[j], a, b00);
                    fma2(w11[j], a, b11);
                    fma2(w01[j], a, b01);
                    fma2(w10[j], a, b10);
                }
            }

            // combine messages
#pragma unroll
            for (int j = 0; j < 4; j++) {
                const float cub = __shfl_sync(FULL, cu_, j);
                const float sxb = __shfl_sync(FULL, sx_, j);
                const float syb = __shfl_sync(FULL, sy_, j);
                const float szb = __shfl_sync(FULL, sz_, j);
                ull d = mul2(ghx[j], dup2(sxb));
                fma2(d, ghy[j], dup2(syb));
                fma2(d, ghz[j], dup2(szb));
                ull t = mul2(w00[j], gh0[j]);
                fma2(t, w11[j], d);
                fma2(m0, t, dup2(cub));
                ull p = mul2(w01[j], gh0[j]);
                fma2(m1x, p, dup2(cub * sxb));
                fma2(m1y, p, dup2(cub * syb));
                fma2(m1z, p, dup2(cub * szb));
                ull q = mul2(w10[j], dup2(cub));
                fma2(m1x, q, ghx[j]);
                fma2(m1y, q, ghy[j]);
                fma2(m1z, q, ghz[j]);
            }
            __syncwarp();   // protect sH before next batch overwrites
        }

        const ull inv = dup2(1.f / 16.f);
        *(ull*)(g_T0 + (size_t)node * 64 + l2) = mul2(m0, inv);
        float* t1 = g_T1 + (size_t)node * 192 + l2;
        *(ull*)t1         = mul2(m1x, inv);
        *(ull*)(t1 + 64)  = mul2(m1y, inv);
        *(ull*)(t1 + 128) = mul2(m1z, inv);
    }
}

// ============================================================
// Epilogue 0: out[n][0:64] = mi0 ; out[n][256:320] = mi0 @ Wsc0[s]
// warp-autonomous, Wsc0 resident in smem
// ============================================================
__global__ void __launch_bounds__(256) node0_kernel(
    const float* __restrict__ attrs, const float* __restrict__ Wsc0,
    float* __restrict__ out) {
    extern __shared__ float sm[];
    float* sW  = sm;              // 40960
    float* sMi = sm + 40960;      // 8 warps * 64
    const int tid = threadIdx.x, wid = tid >> 5, lane = tid & 31;
    const int l2 = 2 * lane;
    const unsigned FULL = 0xffffffffu;
    for (int i = tid; i < SS * CC * CC; i += 256) sW[i] = Wsc0[i];
    __syncthreads();

    float* sMiW = sMi + wid * 64;
    for (int node = blockIdx.x * 8 + wid; node < NN; node += gridDim.x * 8) {
        const ull mi = *(const ull*)(g_T0 + (size_t)node * 64 + l2);
        *(ull*)(sMiW + l2) = mi;
        const float av = (lane < SS) ? attrs[(size_t)node * SS + lane] : 0.f;
        const unsigned bal = __ballot_sync(FULL, av > 0.5f);
        int s = __ffs(bal) - 1;
        if (s < 0) s = 0;
        __syncwarp();
        const float* W = sW + s * 4096 + l2;
        ull A = 0;
#pragma unroll 8
        for (int c = 0; c < 64; c++)
            fma2(A, dup2(sMiW[c]), *(const ull*)(W + c * 64));
        float* orow = out + (size_t)node * 512;
        *(ull*)(orow + l2)       = mi;
        *(ull*)(orow + 256 + l2) = A;
        __syncwarp();
    }
}

// ============================================================
// Epilogue 1: out[n][64+c*3+i] = mi1 ; out[n][320+o*3+i] = res1
// ============================================================
__global__ void __launch_bounds__(256) node1_kernel(
    const float* __restrict__ attrs, const float* __restrict__ Wsc1,
    float* __restrict__ out) {
    extern __shared__ float sm[];
    float* sW  = sm;              // 40960
    float* sMi = sm + 40960;      // 8 warps * 192
    const int tid = threadIdx.x, wid = tid >> 5, lane = tid & 31;
    const int l2 = 2 * lane;
    const unsigned FULL = 0xffffffffu;
    for (int i = tid; i < SS * CC * CC; i += 256) sW[i] = Wsc1[i];
    __syncthreads();

    float* sMiW = sMi + wid * 192;
    for (int node = blockIdx.x * 8 + wid; node < NN; node += gridDim.x * 8) {
        const float* t1 = g_T1 + (size_t)node * 192 + l2;
        const ull mx = *(const ull*)t1;
        const ull my = *(const ull*)(t1 + 64);
        const ull mz = *(const ull*)(t1 + 128);
        *(ull*)(sMiW + l2)        = mx;
        *(ull*)(sMiW + 64 + l2)   = my;
        *(ull*)(sMiW + 128 + l2)  = mz;
        const float av = (lane < SS) ? attrs[(size_t)node * SS + lane] : 0.f;
        const unsigned bal = __ballot_sync(FULL, av > 0.5f);
        int s = __ffs(bal) - 1;
        if (s < 0) s = 0;
        __syncwarp();
        const float* W = sW + s * 4096 + l2;
        ull A0 = 0, A1 = 0, A2 = 0;
#pragma unroll 8
        for (int c = 0; c < 64; c++) {
            const ull wv = *(const ull*)(W + c * 64);
            fma2(A0, dup2(sMiW[c]), wv);
            fma2(A1, dup2(sMiW[64 + c]), wv);
            fma2(A2, dup2(sMiW[128 + c]), wv);
        }
        float x0, x1, y0, y1, z0, z1;
        unpack2(mx, x0, x1); unpack2(my, y0, y1); unpack2(mz, z0, z1);
        float* orow = out + (size_t)node * 512;
        float* om = orow + 64 + 6 * lane;
        om[0] = x0; om[1] = y0; om[2] = z0;
        om[3] = x1; om[4] = y1; om[5] = z1;
        unpack2(A0, x0, x1); unpack2(A1, y0, y1); unpack2(A2, z0, z1);
        float* orr = orow + 320 + 6 * lane;
        orr[0] = x0; orr[1] = y0; orr[2] = z0;
        orr[3] = x1; orr[4] = y1; orr[5] = z1;
        __syncwarp();
    }
}

// ============================================================
extern "C" void kernel_launch(void* const* d_in, const int* in_sizes, int n_in,
                              void* d_out, int out_size) {
    const float* nf0   = (const float*)d_in[0];
    const float* nf1   = (const float*)d_in[1];
    const float* attrs = (const float*)d_in[2];
    const float* ef    = (const float*)d_in[3];
    const float* ea1   = (const float*)d_in[4];
    const float* cut   = (const float*)d_in[5];
    const float* Wup0  = (const float*)d_in[6];
    const float* Wup1  = (const float*)d_in[7];
    const float* W1    = (const float*)d_in[8];
    const float* W2    = (const float*)d_in[9];
    const float* Wsc0  = (const float*)d_in[10];
    const float* Wsc1  = (const float*)d_in[11];
    // d_in[12], d_in[13] are Q0/Q1 identity projectors (no-op)
    const int*   ei    = (const int*)d_in[14];
    float* out = (float*)d_out;

    const int up_smem   = 16384 * 4;                        // 64 KB
    const int node_smem = (512 + 16384 + 1024) * 4;         // 71.7 KB
    const int c0_smem   = (40960 + 512) * 4;                // 166 KB
    const int c1_smem   = (40960 + 1536) * 4;               // 170 KB
    cudaFuncSetAttribute(up_kernel,    cudaFuncAttributeMaxDynamicSharedMemorySize, up_smem);
    cudaFuncSetAttribute(node_kernel,  cudaFuncAttributeMaxDynamicSharedMemorySize, node_smem);
    cudaFuncSetAttribute(node0_kernel, cudaFuncAttributeMaxDynamicSharedMemorySize, c0_smem);
    cudaFuncSetAttribute(node1_kernel, cudaFuncAttributeMaxDynamicSharedMemorySize, c1_smem);

    zero_deg_kernel<<<(NN + 255) / 256, 256>>>();
    hist_kernel<<<EE / 256, 256>>>(ei);
    scan_kernel<<<1, 1024>>>();
    scatter_kernel<<<EE / 256, 256>>>(ei);
    up_kernel<<<(NN + 31) / 32, 256, up_smem>>>(nf0, nf1, Wup0, Wup1);
    node_kernel<<<444, 128, node_smem>>>(ef, ea1, cut, W1, W2, ei);
    node0_kernel<<<296, 256, c0_smem>>>(attrs, Wsc0, out);
    node1_kernel<<<296, 256, c1_smem>>>(attrs, Wsc1, out);
}